// round 1
// baseline (speedup 1.0000x reference)
#include <cuda_runtime.h>
#include <math.h>

#define B_ 4
#define N_ 2048
#define C_ 64
#define H_ 512
#define W_ 512
#define GS 8
#define HG 64
#define WG 64
#define M_ 4096
#define EPSF 1e-8f

// ---------------- scratch (no allocations allowed) ----------------
__device__ float g_cells[B_ * M_ * C_];   // normalized cell descriptors [b][m][c]
__device__ float g_cn[B_ * M_];           // sum of squares of normalized cells
__device__ float g_dpos[B_ * N_];         // positive distances
__device__ float g_an[B_ * N_];           // sum kp1_desc^2
__device__ float g_part[B_ * (N_ / 64)];  // per-block loss partials (128)

// ---------------- 1) 8x8 average pooling -> raw cells [b][m][c] ----------------
__global__ void pool_kernel(const float* __restrict__ desc2) {
    int col = threadIdx.x;        // 0..511
    int hg  = blockIdx.x;         // 0..63
    int c   = blockIdx.y;         // 0..63
    int b   = blockIdx.z;         // 0..3
    const float* p = desc2 + (((size_t)(b * C_ + c) * H_) + hg * GS) * W_ + col;
    float s = 0.f;
#pragma unroll
    for (int r = 0; r < GS; r++) s += p[(size_t)r * W_];
    // reduce groups of 8 consecutive lanes (one 8-wide cell)
    s += __shfl_xor_sync(0xffffffffu, s, 1);
    s += __shfl_xor_sync(0xffffffffu, s, 2);
    s += __shfl_xor_sync(0xffffffffu, s, 4);
    if ((col & 7) == 0) {
        int wg = col >> 3;
        g_cells[((size_t)b * M_ + hg * WG + wg) * C_ + c] = s * (1.0f / 64.0f);
    }
}

// ---------------- 2) normalize cells, compute cn ----------------
__global__ void norm_kernel() {
    int idx  = blockIdx.x;   // b*M + m
    int lane = threadIdx.x;  // 32
    float* p = g_cells + (size_t)idx * C_;
    float v0 = p[lane], v1 = p[lane + 32];
    float ss = v0 * v0 + v1 * v1;
#pragma unroll
    for (int o = 16; o; o >>= 1) ss += __shfl_xor_sync(0xffffffffu, ss, o);
    float inv = 1.0f / (sqrtf(ss) + EPSF);
    p[lane]      = v0 * inv;
    p[lane + 32] = v1 * inv;
    if (lane == 0) g_cn[idx] = ss * inv * inv;
}

// ---------------- 3) bilinear positive sample -> d_pos, an ----------------
__global__ void pos_kernel(const float* __restrict__ wkp,
                           const float* __restrict__ kdesc,
                           const float* __restrict__ desc2) {
    int idx  = blockIdx.x;  // b*N + n
    int b    = idx / N_;
    int lane = threadIdx.x; // 32

    float x = wkp[(size_t)idx * 2 + 0];
    float y = wkp[(size_t)idx * 2 + 1];
    x = fminf(fmaxf(x, 0.0f), (float)(W_ - 1));
    y = fminf(fmaxf(y, 0.0f), (float)(H_ - 1));
    float x0f = floorf(x), y0f = floorf(y);
    int x0 = (int)x0f, y0 = (int)y0f;
    int x1 = min(x0 + 1, W_ - 1), y1 = min(y0 + 1, H_ - 1);
    float wx = x - x0f, wy = y - y0f;
    float w00 = (1.f - wy) * (1.f - wx);
    float w01 = (1.f - wy) * wx;
    float w10 = wy * (1.f - wx);
    float w11 = wy * wx;

    float v[2];
    float ss = 0.f;
#pragma unroll
    for (int q = 0; q < 2; q++) {
        int c = lane + q * 32;
        const float* p = desc2 + ((size_t)(b * C_ + c) * H_) * W_;
        float f00 = p[(size_t)y0 * W_ + x0];
        float f01 = p[(size_t)y0 * W_ + x1];
        float f10 = p[(size_t)y1 * W_ + x0];
        float f11 = p[(size_t)y1 * W_ + x1];
        v[q] = w00 * f00 + w01 * f01 + w10 * f10 + w11 * f11;
        ss += v[q] * v[q];
    }
#pragma unroll
    for (int o = 16; o; o >>= 1) ss += __shfl_xor_sync(0xffffffffu, ss, o);
    float inv = 1.0f / (sqrtf(ss) + EPSF);

    float dsum = 0.f, asum = 0.f;
#pragma unroll
    for (int q = 0; q < 2; q++) {
        int c = lane + q * 32;
        float av = kdesc[(size_t)idx * C_ + c];
        float d  = av - v[q] * inv;
        dsum += d * d;
        asum += av * av;
    }
#pragma unroll
    for (int o = 16; o; o >>= 1) {
        dsum += __shfl_xor_sync(0xffffffffu, dsum, o);
        asum += __shfl_xor_sync(0xffffffffu, asum, o);
    }
    if (lane == 0) {
        g_dpos[idx] = sqrtf(dsum + EPSF);
        g_an[idx]   = asum;
    }
}

// ---------------- 4) distance "GEMM" + mask + top-4 + loss partials ----------------
// Tile: 64 keypoints x 64 cells per iteration, micro 4x4 per thread, 256 threads.
// Select on SQUARED distance (monotone under sqrt(max(.,0)+eps)); sqrt only for 4 finalists.
#define SA 68  // padded shared row stride (multiple of 4 for float4 alignment)

__device__ __forceinline__ void ins4(float (&t)[4], float d2) {
    if (d2 < t[3]) {
        if (d2 < t[2]) {
            t[3] = t[2];
            if (d2 < t[1]) {
                t[2] = t[1];
                if (d2 < t[0]) { t[1] = t[0]; t[0] = d2; }
                else t[1] = d2;
            } else t[2] = d2;
        } else t[3] = d2;
    }
}

__global__ __launch_bounds__(256, 2) void main_kernel(const float* __restrict__ kdesc,
                                                      const float* __restrict__ wkp) {
    __shared__ float aT[C_ * SA];   // aT[c][n], 64 keypoints
    __shared__ float bT[C_ * SA];   // bT[c][m], 64 cells (reused as reduce buffer)
    __shared__ float cns[64];

    int b     = blockIdx.y;
    int nbase = blockIdx.x * 64;
    int tid   = threadIdx.x;
    int tx    = tid & 15;   // m dimension (16 * 4 = 64)
    int ty    = tid >> 4;   // n dimension (16 * 4 = 64)

    const float* A = kdesc + ((size_t)b * N_ + nbase) * C_;
    for (int i = tid; i < 64 * C_; i += 256) {
        int n = i >> 6, c = i & 63;
        aT[c * SA + n] = A[i];
    }

    float wx[4], wy[4], anr[4];
#pragma unroll
    for (int i = 0; i < 4; i++) {
        int n  = nbase + ty * 4 + i;
        wx[i]  = wkp[((size_t)b * N_ + n) * 2 + 0];
        wy[i]  = wkp[((size_t)b * N_ + n) * 2 + 1];
        anr[i] = g_an[b * N_ + n];
    }
    float cx[4];
#pragma unroll
    for (int j = 0; j < 4; j++) cx[j] = ((float)(tx * 4 + j) + 0.5f) * 8.0f;

    float t4[4][4];
#pragma unroll
    for (int i = 0; i < 4; i++)
#pragma unroll
        for (int q = 0; q < 4; q++) t4[i][q] = 3.0e38f;

    const float* CELL = g_cells + (size_t)b * M_ * C_;

    for (int mt = 0; mt < M_ / 64; mt++) {
        int mbase = mt * 64;
        __syncthreads();
        for (int i = tid; i < 64 * C_; i += 256) {
            int mm = i >> 6, c = i & 63;
            bT[c * SA + mm] = CELL[(size_t)(mbase + mm) * C_ + c];
        }
        if (tid < 64) cns[tid] = g_cn[b * M_ + mbase + tid];
        __syncthreads();

        float acc[4][4];
#pragma unroll
        for (int i = 0; i < 4; i++)
#pragma unroll
            for (int j = 0; j < 4; j++) acc[i][j] = 0.f;

#pragma unroll 8
        for (int c = 0; c < C_; c++) {
            float4 av = *(const float4*)(aT + c * SA + ty * 4);
            float4 bv = *(const float4*)(bT + c * SA + tx * 4);
            float aa[4] = {av.x, av.y, av.z, av.w};
            float bb[4] = {bv.x, bv.y, bv.z, bv.w};
#pragma unroll
            for (int i = 0; i < 4; i++)
#pragma unroll
                for (int j = 0; j < 4; j++)
                    acc[i][j] = fmaf(aa[i], bb[j], acc[i][j]);
        }

        // epilogue: squared distance + center-radius mask + top-4 update
        float cy = ((float)mt + 0.5f) * 8.0f;  // hg == mt for this tile
#pragma unroll
        for (int i = 0; i < 4; i++) {
            float dy  = wy[i] - cy;
            float dy2 = dy * dy;
#pragma unroll
            for (int j = 0; j < 4; j++) {
                float d2 = anr[i] + cns[tx * 4 + j] - 2.0f * acc[i][j];
                float dx = wx[i] - cx[j];
                if (fmaf(dx, dx, dy2) <= 64.0f) d2 = 3.0e38f;
                ins4(t4[i], d2);
            }
        }
    }

    __syncthreads();
    // gather 16 lanes x top4 per row into shared, stride 65 (conflict-free-ish)
#pragma unroll
    for (int i = 0; i < 4; i++)
#pragma unroll
        for (int q = 0; q < 4; q++)
            bT[(ty * 4 + i) * 65 + tx * 4 + q] = t4[i][q];
    __syncthreads();

    if (tid < 64) {
        float best[4] = {3.0e38f, 3.0e38f, 3.0e38f, 3.0e38f};
        for (int q = 0; q < 64; q++) ins4(best, bT[tid * 65 + q]);
        float dp = g_dpos[b * N_ + nbase + tid];
        float contrib = 0.f;
#pragma unroll
        for (int q = 0; q < 4; q++) {
            float v = best[q];
            // masked entries -> reference distance 1e6 (relu term is 0 either way)
            float d = (v > 1.0e37f) ? 1.0e6f : sqrtf(fmaxf(v, 0.f) + EPSF);
            contrib += fmaxf(dp - d + 1.0f, 0.f);
        }
        aT[tid] = contrib;
    }
    __syncthreads();
    if (tid == 0) {
        float s = 0.f;
        for (int q = 0; q < 64; q++) s += aT[q];  // fixed order: deterministic
        g_part[b * (N_ / 64) + blockIdx.x] = s;
    }
}

// ---------------- 5) final deterministic reduction ----------------
__global__ void final_kernel(float* __restrict__ out) {
    __shared__ float s[128];
    int t = threadIdx.x;
    s[t] = g_part[t];
    __syncthreads();
#pragma unroll
    for (int o = 64; o; o >>= 1) {
        if (t < o) s[t] += s[t + o];
        __syncthreads();
    }
    if (t == 0) out[0] = s[0] * (1.0f / (float)(B_ * N_ * 4));
}

// ---------------- launch ----------------
extern "C" void kernel_launch(void* const* d_in, const int* in_sizes, int n_in,
                              void* d_out, int out_size) {
    // metadata order: kp1, w_kp1, kp1_desc, desc2, homo12
    const float* wkp   = (const float*)d_in[1];
    const float* kdesc = (const float*)d_in[2];
    const float* desc2 = (const float*)d_in[3];

    pool_kernel<<<dim3(HG, C_, B_), W_>>>(desc2);
    norm_kernel<<<B_ * M_, 32>>>();
    pos_kernel<<<B_ * N_, 32>>>(wkp, kdesc, desc2);
    main_kernel<<<dim3(N_ / 64, B_), 256>>>(kdesc, wkp);
    final_kernel<<<1, 128>>>((float*)d_out);
}

// round 2
// speedup vs baseline: 1.4257x; 1.4257x over previous
#include <cuda_runtime.h>
#include <math.h>

#define B_ 4
#define N_ 2048
#define C_ 64
#define H_ 512
#define W_ 512
#define GS 8
#define HG 64
#define WG 64
#define M_ 4096
#define EPSF 1e-8f

#define TN 64          // keypoints per block
#define TM 128         // cells per m-tile
#define MSPLIT 8       // M chunks (grid.y)
#define MT_PER 4       // m-tiles per block (4096 / 128 / 8)

// ---------------- scratch ----------------
__device__ float g_cells[B_ * M_ * C_];     // normalized cell descriptors [b][m][c]
__device__ float g_cn[B_ * M_];             // ||cell||^2 (post-norm)
__device__ float g_dpos[B_ * N_];
__device__ float g_an[B_ * N_];
__device__ float g_top4[B_ * N_ * MSPLIT * 4];  // per-chunk top-4 of (cn - 2 dot)
__device__ float g_part2[32];

typedef unsigned long long ull;

__device__ __forceinline__ ull pack2(float x) {
    ull r; asm("mov.b64 %0, {%1, %1};" : "=l"(r) : "f"(x)); return r;
}
__device__ __forceinline__ ull ffma2(ull a, ull b, ull c) {
    ull d; asm("fma.rn.f32x2 %0, %1, %2, %3;" : "=l"(d) : "l"(a), "l"(b), "l"(c)); return d;
}
__device__ __forceinline__ void unpack2(ull v, float& lo, float& hi) {
    asm("mov.b64 {%0, %1}, %2;" : "=f"(lo), "=f"(hi) : "l"(v));
}

__device__ __forceinline__ void ins4(float (&t)[4], float d2) {
    if (d2 < t[3]) {
        if (d2 < t[2]) {
            t[3] = t[2];
            if (d2 < t[1]) {
                t[2] = t[1];
                if (d2 < t[0]) { t[1] = t[0]; t[0] = d2; }
                else t[1] = d2;
            } else t[2] = d2;
        } else t[3] = d2;
    }
}

// ---------------- 1) 8x8 average pooling ----------------
__global__ void pool_kernel(const float* __restrict__ desc2) {
    int col = threadIdx.x;
    int hg  = blockIdx.x;
    int c   = blockIdx.y;
    int b   = blockIdx.z;
    const float* p = desc2 + (((size_t)(b * C_ + c) * H_) + hg * GS) * W_ + col;
    float s = 0.f;
#pragma unroll
    for (int r = 0; r < GS; r++) s += p[(size_t)r * W_];
    s += __shfl_xor_sync(0xffffffffu, s, 1);
    s += __shfl_xor_sync(0xffffffffu, s, 2);
    s += __shfl_xor_sync(0xffffffffu, s, 4);
    if ((col & 7) == 0) {
        int wg = col >> 3;
        g_cells[((size_t)b * M_ + hg * WG + wg) * C_ + c] = s * (1.0f / 64.0f);
    }
}

// ---------------- 2) normalize cells ----------------
__global__ void norm_kernel() {
    int idx  = blockIdx.x;
    int lane = threadIdx.x;
    float* p = g_cells + (size_t)idx * C_;
    float v0 = p[lane], v1 = p[lane + 32];
    float ss = v0 * v0 + v1 * v1;
#pragma unroll
    for (int o = 16; o; o >>= 1) ss += __shfl_xor_sync(0xffffffffu, ss, o);
    float inv = 1.0f / (sqrtf(ss) + EPSF);
    p[lane]      = v0 * inv;
    p[lane + 32] = v1 * inv;
    if (lane == 0) g_cn[idx] = ss * inv * inv;
}

// ---------------- 3) positive sample ----------------
__global__ void pos_kernel(const float* __restrict__ wkp,
                           const float* __restrict__ kdesc,
                           const float* __restrict__ desc2) {
    int idx  = blockIdx.x;
    int b    = idx / N_;
    int lane = threadIdx.x;

    float x = wkp[(size_t)idx * 2 + 0];
    float y = wkp[(size_t)idx * 2 + 1];
    x = fminf(fmaxf(x, 0.0f), (float)(W_ - 1));
    y = fminf(fmaxf(y, 0.0f), (float)(H_ - 1));
    float x0f = floorf(x), y0f = floorf(y);
    int x0 = (int)x0f, y0 = (int)y0f;
    int x1 = min(x0 + 1, W_ - 1), y1 = min(y0 + 1, H_ - 1);
    float wx = x - x0f, wy = y - y0f;
    float w00 = (1.f - wy) * (1.f - wx);
    float w01 = (1.f - wy) * wx;
    float w10 = wy * (1.f - wx);
    float w11 = wy * wx;

    float v[2];
    float ss = 0.f;
#pragma unroll
    for (int q = 0; q < 2; q++) {
        int c = lane + q * 32;
        const float* p = desc2 + ((size_t)(b * C_ + c) * H_) * W_;
        float f00 = p[(size_t)y0 * W_ + x0];
        float f01 = p[(size_t)y0 * W_ + x1];
        float f10 = p[(size_t)y1 * W_ + x0];
        float f11 = p[(size_t)y1 * W_ + x1];
        v[q] = w00 * f00 + w01 * f01 + w10 * f10 + w11 * f11;
        ss += v[q] * v[q];
    }
#pragma unroll
    for (int o = 16; o; o >>= 1) ss += __shfl_xor_sync(0xffffffffu, ss, o);
    float inv = 1.0f / (sqrtf(ss) + EPSF);

    float dsum = 0.f, asum = 0.f;
#pragma unroll
    for (int q = 0; q < 2; q++) {
        int c = lane + q * 32;
        float av = kdesc[(size_t)idx * C_ + c];
        float d  = av - v[q] * inv;
        dsum += d * d;
        asum += av * av;
    }
#pragma unroll
    for (int o = 16; o; o >>= 1) {
        dsum += __shfl_xor_sync(0xffffffffu, dsum, o);
        asum += __shfl_xor_sync(0xffffffffu, asum, o);
    }
    if (lane == 0) {
        g_dpos[idx] = sqrtf(dsum + EPSF);
        g_an[idx]   = asum;
    }
}

// ---------------- 4) distance GEMM (f32x2) + mask + top-4 per chunk ----------------
// Block: 64 n x (MT_PER x 128 m), 256 threads, micro 4n x 8m (m packed as 4 f32x2).
__global__ __launch_bounds__(256, 2) void main_kernel(const float* __restrict__ kdesc,
                                                      const float* __restrict__ wkp) {
    __shared__ float smem[12288];          // aT: [c][64n] @0 (4096), bT: [c][128m] @4096 (8192)
    float* aT = smem;
    float* bT = smem + 4096;

    int b     = blockIdx.z;
    int chunk = blockIdx.y;
    int nbase = blockIdx.x * TN;
    int tid   = threadIdx.x;
    int tx    = tid & 15;     // m: 8 cells
    int ty    = tid >> 4;     // n: 4 keypoints

    // fill aT (transpose): float4 read, scalar write (conflict-free: banks = n%32)
    const float4* A4 = (const float4*)(kdesc + ((size_t)b * N_ + nbase) * C_);
#pragma unroll
    for (int u = tid; u < 64 * 16; u += 256) {
        int n = u & 63, c4 = u >> 6;
        float4 v = A4[n * 16 + c4];
        aT[(4 * c4 + 0) * 64 + n] = v.x;
        aT[(4 * c4 + 1) * 64 + n] = v.y;
        aT[(4 * c4 + 2) * 64 + n] = v.z;
        aT[(4 * c4 + 3) * 64 + n] = v.w;
    }

    float wx[4], wy[4];
#pragma unroll
    for (int i = 0; i < 4; i++) {
        int n = nbase + ty * 4 + i;
        wx[i] = wkp[((size_t)b * N_ + n) * 2 + 0];
        wy[i] = wkp[((size_t)b * N_ + n) * 2 + 1];
    }

    float t4[4][4];
#pragma unroll
    for (int i = 0; i < 4; i++)
#pragma unroll
        for (int q = 0; q < 4; q++) t4[i][q] = 3.0e38f;

    const float4* CELL4 = (const float4*)(g_cells + (size_t)b * M_ * C_);
    const float* CN = g_cn + b * M_;

    for (int mt = 0; mt < MT_PER; mt++) {
        int mbase = chunk * (MT_PER * TM) + mt * TM;
        __syncthreads();
        // fill bT (transpose)
#pragma unroll
        for (int u = tid; u < 128 * 16; u += 256) {
            int m = u & 127, c4 = u >> 7;
            float4 v = CELL4[(size_t)(mbase + m) * 16 + c4];
            bT[(4 * c4 + 0) * 128 + m] = v.x;
            bT[(4 * c4 + 1) * 128 + m] = v.y;
            bT[(4 * c4 + 2) * 128 + m] = v.z;
            bT[(4 * c4 + 3) * 128 + m] = v.w;
        }
        __syncthreads();

        ull acc[4][4];
#pragma unroll
        for (int i = 0; i < 4; i++)
#pragma unroll
            for (int j = 0; j < 4; j++) acc[i][j] = 0ull;

        const float* ap_ = aT + ty * 4;
        const float* bp_ = bT + tx * 8;
#pragma unroll 16
        for (int c = 0; c < C_; c++) {
            float4 av = *(const float4*)(ap_ + c * 64);
            ulonglong2 b01 = *(const ulonglong2*)(bp_ + c * 128);
            ulonglong2 b23 = *(const ulonglong2*)(bp_ + c * 128 + 4);
            ull ap0 = pack2(av.x), ap1 = pack2(av.y), ap2 = pack2(av.z), ap3 = pack2(av.w);
            acc[0][0] = ffma2(ap0, b01.x, acc[0][0]);
            acc[0][1] = ffma2(ap0, b01.y, acc[0][1]);
            acc[0][2] = ffma2(ap0, b23.x, acc[0][2]);
            acc[0][3] = ffma2(ap0, b23.y, acc[0][3]);
            acc[1][0] = ffma2(ap1, b01.x, acc[1][0]);
            acc[1][1] = ffma2(ap1, b01.y, acc[1][1]);
            acc[1][2] = ffma2(ap1, b23.x, acc[1][2]);
            acc[1][3] = ffma2(ap1, b23.y, acc[1][3]);
            acc[2][0] = ffma2(ap2, b01.x, acc[2][0]);
            acc[2][1] = ffma2(ap2, b01.y, acc[2][1]);
            acc[2][2] = ffma2(ap2, b23.x, acc[2][2]);
            acc[2][3] = ffma2(ap2, b23.y, acc[2][3]);
            acc[3][0] = ffma2(ap3, b01.x, acc[3][0]);
            acc[3][1] = ffma2(ap3, b01.y, acc[3][1]);
            acc[3][2] = ffma2(ap3, b23.x, acc[3][2]);
            acc[3][3] = ffma2(ap3, b23.y, acc[3][3]);
        }

        // epilogue: select on (cn - 2 dot); mask by center-radius
        int mg0 = mbase + tx * 8;                        // 8 m's stay within one hg row
        float cy = ((float)(mg0 >> 6) + 0.5f) * 8.0f;
        float cn0[8];
        {
            float4 u0 = *(const float4*)(CN + mg0);
            float4 u1 = *(const float4*)(CN + mg0 + 4);
            cn0[0] = u0.x; cn0[1] = u0.y; cn0[2] = u0.z; cn0[3] = u0.w;
            cn0[4] = u1.x; cn0[5] = u1.y; cn0[6] = u1.z; cn0[7] = u1.w;
        }
        float wg0 = (float)(mg0 & 63);
#pragma unroll
        for (int i = 0; i < 4; i++) {
            float dy  = wy[i] - cy;
            float dy2 = dy * dy;
#pragma unroll
            for (int jp = 0; jp < 4; jp++) {
                float f0, f1;
                unpack2(acc[i][jp], f0, f1);
                int k0 = 2 * jp, k1 = 2 * jp + 1;
                float d0 = cn0[k0] - 2.0f * f0;
                float d1 = cn0[k1] - 2.0f * f1;
                float dx0 = wx[i] - (wg0 + (float)k0 + 0.5f) * 8.0f;
                float dx1 = wx[i] - (wg0 + (float)k1 + 0.5f) * 8.0f;
                if (fmaf(dx0, dx0, dy2) <= 64.0f) d0 = 3.0e38f;
                if (fmaf(dx1, dx1, dy2) <= 64.0f) d1 = 3.0e38f;
                ins4(t4[i], d0);
                ins4(t4[i], d1);
            }
        }
    }

    // cross-tx merge via smem (stride 65 -> conflict-free)
    __syncthreads();
#pragma unroll
    for (int i = 0; i < 4; i++)
#pragma unroll
        for (int q = 0; q < 4; q++)
            smem[(ty * 4 + i) * 65 + tx * 4 + q] = t4[i][q];
    __syncthreads();

    if (tid < 64) {
        float best[4] = {3.0e38f, 3.0e38f, 3.0e38f, 3.0e38f};
        const float* row = smem + tid * 65;
        for (int q = 0; q < 64; q++) ins4(best, row[q]);
        size_t o = (((size_t)b * N_ + nbase + tid) * MSPLIT + chunk) * 4;
#pragma unroll
        for (int q = 0; q < 4; q++) g_top4[o + q] = best[q];
    }
}

// ---------------- 5) merge chunks, compute loss partials ----------------
__global__ void merge_kernel() {
    __shared__ float red[256];
    int idx = blockIdx.x * 256 + threadIdx.x;   // keypoint index 0..8191
    float best[4] = {3.0e38f, 3.0e38f, 3.0e38f, 3.0e38f};
    const float* src = g_top4 + (size_t)idx * (MSPLIT * 4);
#pragma unroll
    for (int q = 0; q < MSPLIT * 4; q++) ins4(best, src[q]);
    float an = g_an[idx];
    float dp = g_dpos[idx];
    float contrib = 0.f;
#pragma unroll
    for (int q = 0; q < 4; q++) {
        float v = best[q];
        float d = (v > 1.0e37f) ? 1.0e6f : sqrtf(fmaxf(an + v, 0.f) + EPSF);
        contrib += fmaxf(dp - d + 1.0f, 0.f);
    }
    red[threadIdx.x] = contrib;
    __syncthreads();
#pragma unroll
    for (int o = 128; o; o >>= 1) {
        if (threadIdx.x < o) red[threadIdx.x] += red[threadIdx.x + o];
        __syncthreads();
    }
    if (threadIdx.x == 0) g_part2[blockIdx.x] = red[0];
}

__global__ void final_kernel(float* __restrict__ out) {
    if (threadIdx.x == 0) {
        float s = 0.f;
        for (int q = 0; q < 32; q++) s += g_part2[q];
        out[0] = s * (1.0f / (float)(B_ * N_ * 4));
    }
}

// ---------------- launch ----------------
extern "C" void kernel_launch(void* const* d_in, const int* in_sizes, int n_in,
                              void* d_out, int out_size) {
    const float* wkp   = (const float*)d_in[1];
    const float* kdesc = (const float*)d_in[2];
    const float* desc2 = (const float*)d_in[3];

    pool_kernel<<<dim3(HG, C_, B_), W_>>>(desc2);
    norm_kernel<<<B_ * M_, 32>>>();
    pos_kernel<<<B_ * N_, 32>>>(wkp, kdesc, desc2);
    main_kernel<<<dim3(N_ / TN, MSPLIT, B_), 256>>>(kdesc, wkp);
    merge_kernel<<<32, 256>>>();
    final_kernel<<<1, 32>>>((float*)d_out);
}

// round 5
// speedup vs baseline: 2.5695x; 1.8023x over previous
#include <cuda_runtime.h>
#include <cuda_bf16.h>
#include <cstdint>
#include <math.h>

#define B_ 4
#define N_ 2048
#define C_ 64
#define H_ 512
#define W_ 512
#define GS 8
#define HG 64
#define WG 64
#define M_ 4096
#define EPSF 1e-8f

#define NT 128                 // keypoints per CTA
#define CT 64                  // cell tile per iteration
#define MSPLIT 4
#define CHUNK (M_ / MSPLIT)    // 1024 cells per CTA
#define ITERS (CHUNK / CT)     // 16

// ---------------- scratch ----------------
__device__ float g_cells[B_ * M_ * C_];
__device__ float g_cn[B_ * M_];
__device__ float g_dpos[B_ * N_];
__device__ float g_an[B_ * N_];
__device__ __nv_bfloat16 g_ah[B_ * N_ * C_];
__device__ __nv_bfloat16 g_al[B_ * N_ * C_];
__device__ __nv_bfloat16 g_bh[B_ * M_ * C_];
__device__ __nv_bfloat16 g_bl[B_ * M_ * C_];
__device__ float g_top4[B_ * N_ * MSPLIT * 4];
__device__ float g_part2[32];

__device__ __forceinline__ void mma_bf16(float (&d)[4], const uint32_t (&a)[4],
                                         uint32_t b0, uint32_t b1) {
    asm volatile(
        "mma.sync.aligned.m16n8k16.row.col.f32.bf16.bf16.f32 "
        "{%0,%1,%2,%3}, {%4,%5,%6,%7}, {%8,%9}, {%0,%1,%2,%3};"
        : "+f"(d[0]), "+f"(d[1]), "+f"(d[2]), "+f"(d[3])
        : "r"(a[0]), "r"(a[1]), "r"(a[2]), "r"(a[3]), "r"(b0), "r"(b1));
}

__device__ __forceinline__ void ins4(float (&t)[4], float d2) {
    if (d2 < t[3]) {
        if (d2 < t[2]) {
            t[3] = t[2];
            if (d2 < t[1]) {
                t[2] = t[1];
                if (d2 < t[0]) { t[1] = t[0]; t[0] = d2; }
                else t[1] = d2;
            } else t[2] = d2;
        } else t[3] = d2;
    }
}

// ---------------- 1) 8x8 average pooling ----------------
__global__ void pool_kernel(const float* __restrict__ desc2) {
    int col = threadIdx.x;
    int hg  = blockIdx.x;
    int c   = blockIdx.y;
    int b   = blockIdx.z;
    const float* p = desc2 + (((size_t)(b * C_ + c) * H_) + hg * GS) * W_ + col;
    float s = 0.f;
#pragma unroll
    for (int r = 0; r < GS; r++) s += p[(size_t)r * W_];
    s += __shfl_xor_sync(0xffffffffu, s, 1);
    s += __shfl_xor_sync(0xffffffffu, s, 2);
    s += __shfl_xor_sync(0xffffffffu, s, 4);
    if ((col & 7) == 0) {
        int wg = col >> 3;
        g_cells[((size_t)b * M_ + hg * WG + wg) * C_ + c] = s * (1.0f / 64.0f);
    }
}

// ---------------- 2) normalize cells -> bf16 hi/lo + cn ----------------
__global__ void norm_kernel() {
    int idx  = blockIdx.x;
    int lane = threadIdx.x;
    const float* p = g_cells + (size_t)idx * C_;
    float v0 = p[lane], v1 = p[lane + 32];
    float ss = v0 * v0 + v1 * v1;
#pragma unroll
    for (int o = 16; o; o >>= 1) ss += __shfl_xor_sync(0xffffffffu, ss, o);
    float inv = 1.0f / (sqrtf(ss) + EPSF);
    float n0 = v0 * inv, n1 = v1 * inv;
    __nv_bfloat16 h0 = __float2bfloat16(n0);
    __nv_bfloat16 h1 = __float2bfloat16(n1);
    g_bh[(size_t)idx * C_ + lane]      = h0;
    g_bh[(size_t)idx * C_ + lane + 32] = h1;
    g_bl[(size_t)idx * C_ + lane]      = __float2bfloat16(n0 - __bfloat162float(h0));
    g_bl[(size_t)idx * C_ + lane + 32] = __float2bfloat16(n1 - __bfloat162float(h1));
    if (lane == 0) g_cn[idx] = ss * inv * inv;
}

// ---------------- 2b) kp1_desc -> bf16 hi/lo ----------------
__global__ void conv_a_kernel(const float* __restrict__ kdesc) {
    int i = blockIdx.x * blockDim.x + threadIdx.x;
    float x = kdesc[i];
    __nv_bfloat16 h = __float2bfloat16(x);
    g_ah[i] = h;
    g_al[i] = __float2bfloat16(x - __bfloat162float(h));
}

// ---------------- 3) positive sample -> d_pos, an ----------------
__global__ void pos_kernel(const float* __restrict__ wkp,
                           const float* __restrict__ kdesc,
                           const float* __restrict__ desc2) {
    int idx  = blockIdx.x;
    int b    = idx / N_;
    int lane = threadIdx.x;

    float x = wkp[(size_t)idx * 2 + 0];
    float y = wkp[(size_t)idx * 2 + 1];
    x = fminf(fmaxf(x, 0.0f), (float)(W_ - 1));
    y = fminf(fmaxf(y, 0.0f), (float)(H_ - 1));
    float x0f = floorf(x), y0f = floorf(y);
    int x0 = (int)x0f, y0 = (int)y0f;
    int x1 = min(x0 + 1, W_ - 1), y1 = min(y0 + 1, H_ - 1);
    float wx = x - x0f, wy = y - y0f;
    float w00 = (1.f - wy) * (1.f - wx);
    float w01 = (1.f - wy) * wx;
    float w10 = wy * (1.f - wx);
    float w11 = wy * wx;

    float v[2];
    float ss = 0.f;
#pragma unroll
    for (int q = 0; q < 2; q++) {
        int c = lane + q * 32;
        const float* p = desc2 + ((size_t)(b * C_ + c) * H_) * W_;
        float f00 = p[(size_t)y0 * W_ + x0];
        float f01 = p[(size_t)y0 * W_ + x1];
        float f10 = p[(size_t)y1 * W_ + x0];
        float f11 = p[(size_t)y1 * W_ + x1];
        v[q] = w00 * f00 + w01 * f01 + w10 * f10 + w11 * f11;
        ss += v[q] * v[q];
    }
#pragma unroll
    for (int o = 16; o; o >>= 1) ss += __shfl_xor_sync(0xffffffffu, ss, o);
    float inv = 1.0f / (sqrtf(ss) + EPSF);

    float dsum = 0.f, asum = 0.f;
#pragma unroll
    for (int q = 0; q < 2; q++) {
        int c = lane + q * 32;
        float av = kdesc[(size_t)idx * C_ + c];
        float d  = av - v[q] * inv;
        dsum += d * d;
        asum += av * av;
    }
#pragma unroll
    for (int o = 16; o; o >>= 1) {
        dsum += __shfl_xor_sync(0xffffffffu, dsum, o);
        asum += __shfl_xor_sync(0xffffffffu, asum, o);
    }
    if (lane == 0) {
        g_dpos[idx] = sqrtf(dsum + EPSF);
        g_an[idx]   = asum;
    }
}

// ---------------- 4) HMMA distance GEMM + mask + top-4 ----------------
// 8 warps; warp w owns kp rows [ntile*128 + w*16, +16). B tiles of 64 cells
// staged in smem (144B padded rows -> conflict-free b-fragment LDS).
#define BSTRIDE_W 36   // words per padded cell row (72 bf16 = 144 B)

__global__ void __launch_bounds__(256, 2) mma_kernel(const float* __restrict__ wkp) {
    __shared__ uint4 sm_bh[CT * 9];
    __shared__ uint4 sm_bl[CT * 9];
    __shared__ float cn_s[CHUNK];

    int tid   = threadIdx.x;
    int w     = tid >> 5;
    int lane  = tid & 31;
    int g     = lane >> 2;
    int tig   = lane & 3;
    int ntile = blockIdx.x;
    int chunk = blockIdx.y;
    int b     = blockIdx.z;

    int mbase0 = chunk * CHUNK;

    // preload cn for the whole chunk
#pragma unroll
    for (int u = tid; u < CHUNK; u += 256) cn_s[u] = g_cn[b * M_ + mbase0 + u];

    // A fragments in registers: rows r0 = base + g, r1 = base + g + 8
    int r0 = ntile * NT + w * 16 + g;
    uint32_t ah[4][4], al[4][4];
    {
        const char* Ah = (const char*)(g_ah + ((size_t)b * N_ + r0) * C_);
        const char* Al = (const char*)(g_al + ((size_t)b * N_ + r0) * C_);
#pragma unroll
        for (int ks = 0; ks < 4; ks++) {
            int o0 = (ks * 16 + tig * 2) * 2;
            ah[ks][0] = *(const uint32_t*)(Ah + o0);
            ah[ks][1] = *(const uint32_t*)(Ah + 8 * C_ * 2 + o0);
            ah[ks][2] = *(const uint32_t*)(Ah + o0 + 16);
            ah[ks][3] = *(const uint32_t*)(Ah + 8 * C_ * 2 + o0 + 16);
            al[ks][0] = *(const uint32_t*)(Al + o0);
            al[ks][1] = *(const uint32_t*)(Al + 8 * C_ * 2 + o0);
            al[ks][2] = *(const uint32_t*)(Al + o0 + 16);
            al[ks][3] = *(const uint32_t*)(Al + 8 * C_ * 2 + o0 + 16);
        }
    }

    // keypoint coords for both rows
    float wx0 = wkp[((size_t)b * N_ + r0) * 2 + 0];
    float wy0 = wkp[((size_t)b * N_ + r0) * 2 + 1];
    float wx1 = wkp[((size_t)b * N_ + r0 + 8) * 2 + 0];
    float wy1 = wkp[((size_t)b * N_ + r0 + 8) * 2 + 1];

    float t4a[4] = {3.0e38f, 3.0e38f, 3.0e38f, 3.0e38f};
    float t4b[4] = {3.0e38f, 3.0e38f, 3.0e38f, 3.0e38f};

    const uint4* Bh4 = (const uint4*)(g_bh + ((size_t)b * M_ + mbase0) * C_);
    const uint4* Bl4 = (const uint4*)(g_bl + ((size_t)b * M_ + mbase0) * C_);
    const uint32_t* bh_w = (const uint32_t*)sm_bh;
    const uint32_t* bl_w = (const uint32_t*)sm_bl;

    for (int it = 0; it < ITERS; it++) {
        __syncthreads();
        // fill B tile (hi/lo): 512 uint4 each
#pragma unroll
        for (int u = tid; u < CT * 8; u += 256) {
            int row = u >> 3, seg = u & 7;
            sm_bh[row * 9 + seg] = Bh4[(size_t)(it * CT + row) * 8 + seg];
            sm_bl[row * 9 + seg] = Bl4[(size_t)(it * CT + row) * 8 + seg];
        }
        __syncthreads();

        // hg row for this tile (64-cell aligned)
        float cy  = (float)(chunk * (CHUNK / 64) + it) * 8.0f + 4.0f;
        float dy0 = wy0 - cy, dy02 = dy0 * dy0;
        float dy1 = wy1 - cy, dy12 = dy1 * dy1;

#pragma unroll
        for (int nt = 0; nt < 8; nt++) {
            float acc[4] = {0.f, 0.f, 0.f, 0.f};
            int base = (nt * 8) * BSTRIDE_W + tig;
#pragma unroll
            for (int ks = 0; ks < 4; ks++) {
                uint32_t bh0 = bh_w[base + g * BSTRIDE_W + ks * 8];
                uint32_t bh1 = bh_w[base + g * BSTRIDE_W + ks * 8 + 4];
                uint32_t bl0 = bl_w[base + g * BSTRIDE_W + ks * 8];
                uint32_t bl1 = bl_w[base + g * BSTRIDE_W + ks * 8 + 4];
                mma_bf16(acc, ah[ks], bh0, bh1);
                mma_bf16(acc, ah[ks], bl0, bl1);
                mma_bf16(acc, al[ks], bh0, bh1);
            }
            // epilogue: cols j0 = nt*8 + tig*2, j0+1 ; rows r0 (acc[0,1]) and r0+8 (acc[2,3])
            int jl = nt * 8 + tig * 2;
            float cn0 = cn_s[it * CT + jl];
            float cn1 = cn_s[it * CT + jl + 1];
            float cxa = (float)jl * 8.0f + 4.0f;
            float cxb = cxa + 8.0f;

            float d00 = fmaf(-2.0f, acc[0], cn0);
            float d01 = fmaf(-2.0f, acc[1], cn1);
            float d10 = fmaf(-2.0f, acc[2], cn0);
            float d11 = fmaf(-2.0f, acc[3], cn1);
            float dxa0 = wx0 - cxa, dxb0 = wx0 - cxb;
            float dxa1 = wx1 - cxa, dxb1 = wx1 - cxb;
            if (fmaf(dxa0, dxa0, dy02) <= 64.0f) d00 = 3.0e38f;
            if (fmaf(dxb0, dxb0, dy02) <= 64.0f) d01 = 3.0e38f;
            if (fmaf(dxa1, dxa1, dy12) <= 64.0f) d10 = 3.0e38f;
            if (fmaf(dxb1, dxb1, dy12) <= 64.0f) d11 = 3.0e38f;
            ins4(t4a, d00); ins4(t4a, d01);
            ins4(t4b, d10); ins4(t4b, d11);
        }
    }

    // merge top-4 across the 4 tig lanes of each row.
    // SNAPSHOT the partner's list BEFORE inserting (read-while-mutate hazard:
    // interleaving shfl and ins4 merges against a half-mutated list).
#pragma unroll
    for (int off = 1; off <= 2; off <<= 1) {
        float va[4], vb[4];
#pragma unroll
        for (int q = 0; q < 4; q++) {
            va[q] = __shfl_xor_sync(0xffffffffu, t4a[q], off);
            vb[q] = __shfl_xor_sync(0xffffffffu, t4b[q], off);
        }
#pragma unroll
        for (int q = 0; q < 4; q++) {
            ins4(t4a, va[q]);
            ins4(t4b, vb[q]);
        }
    }

    if (tig == 0) {
        size_t o0 = (((size_t)b * N_ + r0) * MSPLIT + chunk) * 4;
        size_t o1 = (((size_t)b * N_ + r0 + 8) * MSPLIT + chunk) * 4;
#pragma unroll
        for (int q = 0; q < 4; q++) {
            g_top4[o0 + q] = t4a[q];
            g_top4[o1 + q] = t4b[q];
        }
    }
}

// ---------------- 5) merge chunks + loss ----------------
__global__ void merge_kernel() {
    __shared__ float red[256];
    int idx = blockIdx.x * 256 + threadIdx.x;
    float best[4] = {3.0e38f, 3.0e38f, 3.0e38f, 3.0e38f};
    const float* src = g_top4 + (size_t)idx * (MSPLIT * 4);
#pragma unroll
    for (int q = 0; q < MSPLIT * 4; q++) ins4(best, src[q]);
    float an = g_an[idx];
    float dp = g_dpos[idx];
    float contrib = 0.f;
#pragma unroll
    for (int q = 0; q < 4; q++) {
        float v = best[q];
        float d = (v > 1.0e37f) ? 1.0e6f : sqrtf(fmaxf(an + v, 0.f) + EPSF);
        contrib += fmaxf(dp - d + 1.0f, 0.f);
    }
    red[threadIdx.x] = contrib;
    __syncthreads();
#pragma unroll
    for (int o = 128; o; o >>= 1) {
        if (threadIdx.x < o) red[threadIdx.x] += red[threadIdx.x + o];
        __syncthreads();
    }
    if (threadIdx.x == 0) g_part2[blockIdx.x] = red[0];
}

__global__ void final_kernel(float* __restrict__ out) {
    if (threadIdx.x == 0) {
        float s = 0.f;
        for (int q = 0; q < 32; q++) s += g_part2[q];
        out[0] = s * (1.0f / (float)(B_ * N_ * 4));
    }
}

// ---------------- launch ----------------
extern "C" void kernel_launch(void* const* d_in, const int* in_sizes, int n_in,
                              void* d_out, int out_size) {
    const float* wkp   = (const float*)d_in[1];
    const float* kdesc = (const float*)d_in[2];
    const float* desc2 = (const float*)d_in[3];

    pool_kernel<<<dim3(HG, C_, B_), W_>>>(desc2);
    norm_kernel<<<B_ * M_, 32>>>();
    conv_a_kernel<<<(B_ * N_ * C_) / 256, 256>>>(kdesc);
    pos_kernel<<<B_ * N_, 32>>>(wkp, kdesc, desc2);
    mma_kernel<<<dim3(N_ / NT, MSPLIT, B_), 256>>>(wkp);
    merge_kernel<<<32, 256>>>();
    final_kernel<<<1, 32>>>((float*)d_out);
}

// round 6
// speedup vs baseline: 2.7896x; 1.0857x over previous
#include <cuda_runtime.h>
#include <cuda_bf16.h>
#include <cstdint>
#include <math.h>

#define B_ 4
#define N_ 2048
#define C_ 64
#define H_ 512
#define W_ 512
#define GS 8
#define HG 64
#define WG 64
#define M_ 4096
#define EPSF 1e-8f

#define NT 128
#define CT 64
#define MSPLIT 4
#define CHUNK (M_ / MSPLIT)    // 1024
#define ITERS (CHUNK / CT)     // 16

// prep-kernel block ranges (pos/conv first: their latency hides under pool)
#define PB_POS   512                      // 512 blocks x 16 warps = 8192 kp
#define PB_CONV  256                      // 256 x 512 x float4 = 524288 elems
#define PB_POOL  (HG * C_ * B_)           // 16384
#define PREP_GRID (PB_POS + PB_CONV + PB_POOL)

// ---------------- scratch ----------------
__device__ float g_cells[B_ * M_ * C_];
__device__ float g_cn[B_ * M_];
__device__ float g_dpos[B_ * N_];
__device__ float g_an[B_ * N_];
__device__ __nv_bfloat16 g_ah[B_ * N_ * C_];
__device__ __nv_bfloat16 g_al[B_ * N_ * C_];
__device__ __nv_bfloat16 g_bh[B_ * M_ * C_];
__device__ __nv_bfloat16 g_bl[B_ * M_ * C_];
__device__ float g_top4[B_ * N_ * MSPLIT * 4];
__device__ float g_part2[32];

__device__ __forceinline__ void mma_bf16(float (&d)[4], const uint32_t (&a)[4],
                                         uint32_t b0, uint32_t b1) {
    asm volatile(
        "mma.sync.aligned.m16n8k16.row.col.f32.bf16.bf16.f32 "
        "{%0,%1,%2,%3}, {%4,%5,%6,%7}, {%8,%9}, {%0,%1,%2,%3};"
        : "+f"(d[0]), "+f"(d[1]), "+f"(d[2]), "+f"(d[3])
        : "r"(a[0]), "r"(a[1]), "r"(a[2]), "r"(a[3]), "r"(b0), "r"(b1));
}

__device__ __forceinline__ void cp16(uint32_t dst, const void* src) {
    asm volatile("cp.async.cg.shared.global [%0], [%1], 16;" :: "r"(dst), "l"(src));
}
#define CP_COMMIT() asm volatile("cp.async.commit_group;" ::: "memory")
#define CP_WAIT(n)  asm volatile("cp.async.wait_group %0;" :: "n"(n) : "memory")

__device__ __forceinline__ void ins4(float (&t)[4], float d2) {
    if (d2 < t[3]) {
        if (d2 < t[2]) {
            t[3] = t[2];
            if (d2 < t[1]) {
                t[2] = t[1];
                if (d2 < t[0]) { t[1] = t[0]; t[0] = d2; }
                else t[1] = d2;
            } else t[2] = d2;
        } else t[3] = d2;
    }
}

// ---------------- 1) fused prep: pos + conv_a + pool ----------------
__global__ void __launch_bounds__(512) prep_kernel(const float* __restrict__ wkp,
                                                   const float* __restrict__ kdesc,
                                                   const float* __restrict__ desc2) {
    int p   = blockIdx.x;
    int tid = threadIdx.x;

    if (p < PB_POS) {
        // ---- positive bilinear sample: warp per keypoint ----
        int lane = tid & 31;
        int idx  = p * 16 + (tid >> 5);      // 0..8191
        int b    = idx / N_;

        float x = wkp[(size_t)idx * 2 + 0];
        float y = wkp[(size_t)idx * 2 + 1];
        x = fminf(fmaxf(x, 0.0f), (float)(W_ - 1));
        y = fminf(fmaxf(y, 0.0f), (float)(H_ - 1));
        float x0f = floorf(x), y0f = floorf(y);
        int x0 = (int)x0f, y0 = (int)y0f;
        int x1 = min(x0 + 1, W_ - 1), y1 = min(y0 + 1, H_ - 1);
        float wx = x - x0f, wy = y - y0f;
        float w00 = (1.f - wy) * (1.f - wx);
        float w01 = (1.f - wy) * wx;
        float w10 = wy * (1.f - wx);
        float w11 = wy * wx;

        float v[2];
        float ss = 0.f;
#pragma unroll
        for (int q = 0; q < 2; q++) {
            int c = lane + q * 32;
            const float* pp = desc2 + ((size_t)(b * C_ + c) * H_) * W_;
            float f00 = pp[(size_t)y0 * W_ + x0];
            float f01 = pp[(size_t)y0 * W_ + x1];
            float f10 = pp[(size_t)y1 * W_ + x0];
            float f11 = pp[(size_t)y1 * W_ + x1];
            v[q] = w00 * f00 + w01 * f01 + w10 * f10 + w11 * f11;
            ss += v[q] * v[q];
        }
#pragma unroll
        for (int o = 16; o; o >>= 1) ss += __shfl_xor_sync(0xffffffffu, ss, o);
        float inv = 1.0f / (sqrtf(ss) + EPSF);

        float dsum = 0.f, asum = 0.f;
#pragma unroll
        for (int q = 0; q < 2; q++) {
            int c = lane + q * 32;
            float av = kdesc[(size_t)idx * C_ + c];
            float d  = av - v[q] * inv;
            dsum += d * d;
            asum += av * av;
        }
#pragma unroll
        for (int o = 16; o; o >>= 1) {
            dsum += __shfl_xor_sync(0xffffffffu, dsum, o);
            asum += __shfl_xor_sync(0xffffffffu, asum, o);
        }
        if (lane == 0) {
            g_dpos[idx] = sqrtf(dsum + EPSF);
            g_an[idx]   = asum;
        }
    } else if (p < PB_POS + PB_CONV) {
        // ---- kp1_desc -> bf16 hi/lo (float4 granularity) ----
        int i4 = (p - PB_POS) * 512 + tid;            // 0..131071
        float4 v = ((const float4*)kdesc)[i4];
        __nv_bfloat16 hx = __float2bfloat16(v.x);
        __nv_bfloat16 hy = __float2bfloat16(v.y);
        __nv_bfloat16 hz = __float2bfloat16(v.z);
        __nv_bfloat16 hw = __float2bfloat16(v.w);
        __nv_bfloat162 h01, h23, l01, l23;
        h01.x = hx; h01.y = hy; h23.x = hz; h23.y = hw;
        l01.x = __float2bfloat16(v.x - __bfloat162float(hx));
        l01.y = __float2bfloat16(v.y - __bfloat162float(hy));
        l23.x = __float2bfloat16(v.z - __bfloat162float(hz));
        l23.y = __float2bfloat16(v.w - __bfloat162float(hw));
        ((__nv_bfloat162*)g_ah)[i4 * 2]     = h01;
        ((__nv_bfloat162*)g_ah)[i4 * 2 + 1] = h23;
        ((__nv_bfloat162*)g_al)[i4 * 2]     = l01;
        ((__nv_bfloat162*)g_al)[i4 * 2 + 1] = l23;
    } else {
        // ---- 8x8 average pooling ----
        int q2 = p - PB_POS - PB_CONV;
        int hg = q2 & 63;
        int c  = (q2 >> 6) & 63;
        int b  = q2 >> 12;
        int col = tid;
        const float* pp = desc2 + (((size_t)(b * C_ + c) * H_) + hg * GS) * W_ + col;
        float s = 0.f;
#pragma unroll
        for (int r = 0; r < GS; r++) s += pp[(size_t)r * W_];
        s += __shfl_xor_sync(0xffffffffu, s, 1);
        s += __shfl_xor_sync(0xffffffffu, s, 2);
        s += __shfl_xor_sync(0xffffffffu, s, 4);
        if ((col & 7) == 0) {
            int wg = col >> 3;
            g_cells[((size_t)b * M_ + hg * WG + wg) * C_ + c] = s * (1.0f / 64.0f);
        }
    }
}

// ---------------- 2) normalize cells -> bf16 hi/lo + cn ----------------
__global__ void norm_kernel() {
    int idx  = blockIdx.x;
    int lane = threadIdx.x;
    const float* p = g_cells + (size_t)idx * C_;
    float v0 = p[lane], v1 = p[lane + 32];
    float ss = v0 * v0 + v1 * v1;
#pragma unroll
    for (int o = 16; o; o >>= 1) ss += __shfl_xor_sync(0xffffffffu, ss, o);
    float inv = 1.0f / (sqrtf(ss) + EPSF);
    float n0 = v0 * inv, n1 = v1 * inv;
    __nv_bfloat16 h0 = __float2bfloat16(n0);
    __nv_bfloat16 h1 = __float2bfloat16(n1);
    g_bh[(size_t)idx * C_ + lane]      = h0;
    g_bh[(size_t)idx * C_ + lane + 32] = h1;
    g_bl[(size_t)idx * C_ + lane]      = __float2bfloat16(n0 - __bfloat162float(h0));
    g_bl[(size_t)idx * C_ + lane + 32] = __float2bfloat16(n1 - __bfloat162float(h1));
    if (lane == 0) g_cn[idx] = ss * inv * inv;
}

// ---------------- 3) HMMA distance GEMM + mask + top-4 (double buffered) ----------------
#define BSTRIDE_W 36   // words per padded cell row (72 bf16 = 144 B)

__global__ void __launch_bounds__(256, 2) mma_kernel(const float* __restrict__ wkp) {
    __shared__ uint4 sm_bh[2][CT * 9];
    __shared__ uint4 sm_bl[2][CT * 9];
    __shared__ float cn_s[CHUNK];

    int tid   = threadIdx.x;
    int w     = tid >> 5;
    int lane  = tid & 31;
    int g     = lane >> 2;
    int tig   = lane & 3;
    int ntile = blockIdx.x;
    int chunk = blockIdx.y;
    int b     = blockIdx.z;

    int mbase0 = chunk * CHUNK;

#pragma unroll
    for (int u = tid; u < CHUNK; u += 256) cn_s[u] = g_cn[b * M_ + mbase0 + u];

    // A fragments in registers
    int r0 = ntile * NT + w * 16 + g;
    uint32_t ah[4][4], al[4][4];
    {
        const char* Ah = (const char*)(g_ah + ((size_t)b * N_ + r0) * C_);
        const char* Al = (const char*)(g_al + ((size_t)b * N_ + r0) * C_);
#pragma unroll
        for (int ks = 0; ks < 4; ks++) {
            int o0 = (ks * 16 + tig * 2) * 2;
            ah[ks][0] = *(const uint32_t*)(Ah + o0);
            ah[ks][1] = *(const uint32_t*)(Ah + 8 * C_ * 2 + o0);
            ah[ks][2] = *(const uint32_t*)(Ah + o0 + 16);
            ah[ks][3] = *(const uint32_t*)(Ah + 8 * C_ * 2 + o0 + 16);
            al[ks][0] = *(const uint32_t*)(Al + o0);
            al[ks][1] = *(const uint32_t*)(Al + 8 * C_ * 2 + o0);
            al[ks][2] = *(const uint32_t*)(Al + o0 + 16);
            al[ks][3] = *(const uint32_t*)(Al + 8 * C_ * 2 + o0 + 16);
        }
    }

    float wx0 = wkp[((size_t)b * N_ + r0) * 2 + 0];
    float wy0 = wkp[((size_t)b * N_ + r0) * 2 + 1];
    float wx1 = wkp[((size_t)b * N_ + r0 + 8) * 2 + 0];
    float wy1 = wkp[((size_t)b * N_ + r0 + 8) * 2 + 1];

    float t4a[4] = {3.0e38f, 3.0e38f, 3.0e38f, 3.0e38f};
    float t4b[4] = {3.0e38f, 3.0e38f, 3.0e38f, 3.0e38f};

    const uint4* Bh4 = (const uint4*)(g_bh + ((size_t)b * M_ + mbase0) * C_);
    const uint4* Bl4 = (const uint4*)(g_bl + ((size_t)b * M_ + mbase0) * C_);

    // async fill of tile `it` into buffer `buf`
    auto fill = [&](int it, int buf) {
        uint32_t sbh = (uint32_t)__cvta_generic_to_shared(&sm_bh[buf][0]);
        uint32_t sbl = (uint32_t)__cvta_generic_to_shared(&sm_bl[buf][0]);
#pragma unroll
        for (int u = tid; u < CT * 8; u += 256) {
            int row = u >> 3, seg = u & 7;
            uint32_t off = (uint32_t)(row * 9 + seg) * 16;
            cp16(sbh + off, Bh4 + (size_t)(it * CT + row) * 8 + seg);
            cp16(sbl + off, Bl4 + (size_t)(it * CT + row) * 8 + seg);
        }
    };

    fill(0, 0);
    CP_COMMIT();

    for (int it = 0; it < ITERS; it++) {
        int cur = it & 1;
        if (it + 1 < ITERS) {
            fill(it + 1, 1 - cur);
            CP_COMMIT();
            CP_WAIT(1);
        } else {
            CP_WAIT(0);
        }
        __syncthreads();

        const uint32_t* bh_w = (const uint32_t*)sm_bh[cur];
        const uint32_t* bl_w = (const uint32_t*)sm_bl[cur];

        float cy  = (float)(chunk * (CHUNK / 64) + it) * 8.0f + 4.0f;
        float dy0 = wy0 - cy, dy02 = dy0 * dy0;
        float dy1 = wy1 - cy, dy12 = dy1 * dy1;

#pragma unroll
        for (int nt = 0; nt < 8; nt++) {
            float acc[4] = {0.f, 0.f, 0.f, 0.f};
            int base = (nt * 8) * BSTRIDE_W + tig;
#pragma unroll
            for (int ks = 0; ks < 4; ks++) {
                uint32_t bh0 = bh_w[base + g * BSTRIDE_W + ks * 8];
                uint32_t bh1 = bh_w[base + g * BSTRIDE_W + ks * 8 + 4];
                uint32_t bl0 = bl_w[base + g * BSTRIDE_W + ks * 8];
                uint32_t bl1 = bl_w[base + g * BSTRIDE_W + ks * 8 + 4];
                mma_bf16(acc, ah[ks], bh0, bh1);
                mma_bf16(acc, ah[ks], bl0, bl1);
                mma_bf16(acc, al[ks], bh0, bh1);
            }
            int jl = nt * 8 + tig * 2;
            float cn0 = cn_s[it * CT + jl];
            float cn1 = cn_s[it * CT + jl + 1];
            float cxa = (float)jl * 8.0f + 4.0f;
            float cxb = cxa + 8.0f;

            float d00 = fmaf(-2.0f, acc[0], cn0);
            float d01 = fmaf(-2.0f, acc[1], cn1);
            float d10 = fmaf(-2.0f, acc[2], cn0);
            float d11 = fmaf(-2.0f, acc[3], cn1);
            float dxa0 = wx0 - cxa, dxb0 = wx0 - cxb;
            float dxa1 = wx1 - cxa, dxb1 = wx1 - cxb;
            if (fmaf(dxa0, dxa0, dy02) <= 64.0f) d00 = 3.0e38f;
            if (fmaf(dxb0, dxb0, dy02) <= 64.0f) d01 = 3.0e38f;
            if (fmaf(dxa1, dxa1, dy12) <= 64.0f) d10 = 3.0e38f;
            if (fmaf(dxb1, dxb1, dy12) <= 64.0f) d11 = 3.0e38f;
            ins4(t4a, d00); ins4(t4a, d01);
            ins4(t4b, d10); ins4(t4b, d11);
        }
        __syncthreads();   // compute done before buffer refilled next iteration
    }

    // snapshot-based cross-lane top-4 merge (tig lanes)
#pragma unroll
    for (int off = 1; off <= 2; off <<= 1) {
        float va[4], vb[4];
#pragma unroll
        for (int q = 0; q < 4; q++) {
            va[q] = __shfl_xor_sync(0xffffffffu, t4a[q], off);
            vb[q] = __shfl_xor_sync(0xffffffffu, t4b[q], off);
        }
#pragma unroll
        for (int q = 0; q < 4; q++) {
            ins4(t4a, va[q]);
            ins4(t4b, vb[q]);
        }
    }

    if (tig == 0) {
        size_t o0 = (((size_t)b * N_ + r0) * MSPLIT + chunk) * 4;
        size_t o1 = (((size_t)b * N_ + r0 + 8) * MSPLIT + chunk) * 4;
#pragma unroll
        for (int q = 0; q < 4; q++) {
            g_top4[o0 + q] = t4a[q];
            g_top4[o1 + q] = t4b[q];
        }
    }
}

// ---------------- 4) merge chunks + loss ----------------
__global__ void merge_kernel() {
    __shared__ float red[256];
    int idx = blockIdx.x * 256 + threadIdx.x;
    float best[4] = {3.0e38f, 3.0e38f, 3.0e38f, 3.0e38f};
    const float* src = g_top4 + (size_t)idx * (MSPLIT * 4);
#pragma unroll
    for (int q = 0; q < MSPLIT * 4; q++) ins4(best, src[q]);
    float an = g_an[idx];
    float dp = g_dpos[idx];
    float contrib = 0.f;
#pragma unroll
    for (int q = 0; q < 4; q++) {
        float v = best[q];
        float d = (v > 1.0e37f) ? 1.0e6f : sqrtf(fmaxf(an + v, 0.f) + EPSF);
        contrib += fmaxf(dp - d + 1.0f, 0.f);
    }
    red[threadIdx.x] = contrib;
    __syncthreads();
#pragma unroll
    for (int o = 128; o; o >>= 1) {
        if (threadIdx.x < o) red[threadIdx.x] += red[threadIdx.x + o];
        __syncthreads();
    }
    if (threadIdx.x == 0) g_part2[blockIdx.x] = red[0];
}

__global__ void final_kernel(float* __restrict__ out) {
    if (threadIdx.x == 0) {
        float s = 0.f;
        for (int q = 0; q < 32; q++) s += g_part2[q];
        out[0] = s * (1.0f / (float)(B_ * N_ * 4));
    }
}

// ---------------- launch ----------------
extern "C" void kernel_launch(void* const* d_in, const int* in_sizes, int n_in,
                              void* d_out, int out_size) {
    const float* wkp   = (const float*)d_in[1];
    const float* kdesc = (const float*)d_in[2];
    const float* desc2 = (const float*)d_in[3];

    prep_kernel<<<PREP_GRID, 512>>>(wkp, kdesc, desc2);
    norm_kernel<<<B_ * M_, 32>>>();
    mma_kernel<<<dim3(N_ / NT, MSPLIT, B_), 256>>>(wkp);
    merge_kernel<<<32, 256>>>();
    final_kernel<<<1, 32>>>((float*)d_out);
}